// round 6
// baseline (speedup 1.0000x reference)
#include <cuda_runtime.h>
#include <cuda_bf16.h>
#include <cstdint>

// out[0,d,h,w,c] = in[0, z[d], row[h], col[w], 0]
// in (1,128,128,128,32) f32; z/row/col (64,) i32; out (1,64,64,64,32) f32.
//
// Block = 256 threads = 256 spatial positions = 32KB of output.
// Phase 1: 256 independent gathers -> smem.
// Phase 2: replicate into a 32KB smem image of the output chunk.
// Phase 3: single cp.async.bulk (TMA) 32KB smem -> gmem. No per-thread STG.

__device__ __forceinline__ uint32_t smem_u32(const void* p) {
    uint32_t a;
    asm("{ .reg .u64 t; cvta.to.shared.u64 t, %1; cvt.u32.u64 %0, t; }"
        : "=r"(a) : "l"(p));
    return a;
}

__global__ __launch_bounds__(256) void sdown3d_kernel(
    const float* __restrict__ in,
    const int* __restrict__ zi,
    const int* __restrict__ ri,
    const int* __restrict__ ci,
    float4* __restrict__ out)
{
    __shared__ float sval[256];
    __shared__ __align__(128) float4 buf[2048];   // 32KB output image

    const int t = threadIdx.x;
    const int pos = blockIdx.x * 256 + t;          // spatial position
    const int w = pos & 63;
    const int h = (pos >> 6) & 63;
    const int d = pos >> 12;

    // Phase 1: fully independent gather per thread
    int src = (__ldg(zi + d) << 7) + __ldg(ri + h);    // z*128 + row
    src = ((src << 7) + __ldg(ci + w)) << 5;           // (*128 + col)*32
    sval[t] = __ldg(in + src);

    __syncthreads();

    // Phase 2: build the replicated 32KB chunk in smem.
    // float4 index f = j*256+t corresponds to position f>>3 = j*32 + (t>>3).
    #pragma unroll
    for (int j = 0; j < 8; j++) {
        float s = sval[j * 32 + (t >> 3)];
        buf[j * 256 + t] = make_float4(s, s, s, s);
    }

    __syncthreads();

    // Phase 3: one TMA bulk store of the whole chunk.
    if (t == 0) {
        asm volatile("fence.proxy.async.shared::cta;" ::: "memory");
        uint32_t s = smem_u32(buf);
        const float4* dst = out + (size_t)blockIdx.x * 2048;
        asm volatile(
            "cp.async.bulk.global.shared::cta.bulk_group [%0], [%1], %2;"
            :: "l"(dst), "r"(s), "n"(32768) : "memory");
        asm volatile("cp.async.bulk.commit_group;" ::: "memory");
        asm volatile("cp.async.bulk.wait_group 0;" ::: "memory");
    }
}

extern "C" void kernel_launch(void* const* d_in, const int* in_sizes, int n_in,
                              void* d_out, int out_size)
{
    const float* in  = (const float*)d_in[0];
    const int*   zi  = (const int*)d_in[1];
    const int*   ri  = (const int*)d_in[2];
    const int*   ci  = (const int*)d_in[3];
    float4*      out = (float4*)d_out;

    // 64^3 = 262144 positions / 256 per block = 1024 blocks
    sdown3d_kernel<<<1024, 256>>>(in, zi, ri, ci, out);
}